// round 1
// baseline (speedup 1.0000x reference)
#include <cuda_runtime.h>

#define BATCH 4
#define SEQ   2048
#define HID   1024
#define NFREQ 513               // HID/2 + 1
#define KP    1032              // 2*NFREQ padded up to multiple of 8 (pad = zeros)
#define ROWS  (BATCH * SEQ)     // 8192

// Scratch (static device globals — allocation-free, graph-capturable)
__device__ float g_qn[(size_t)ROWS * KP];            // [cos | sin | 0-pad] per row
__device__ float g_kn[(size_t)ROWS * KP];
__device__ float g_w [(size_t)BATCH * SEQ * SEQ];    // scores -> weights (in place)

// ---------------------------------------------------------------------------
// 1) FFT-1024 per row + unit-normalize bins -> packed [cos(phase) | sin(phase)]
//    blockIdx.x = row (0..8191), blockIdx.y = 0 (Q) / 1 (K). 512 threads.
// ---------------------------------------------------------------------------
__global__ void fft_phase_kernel(const float* __restrict__ Q,
                                 const float* __restrict__ Kin) {
    __shared__ float2 sh[1024];
    const int row = blockIdx.x;
    const float* src = (blockIdx.y == 0) ? Q : Kin;
    float* dst = (blockIdx.y == 0) ? g_qn : g_kn;
    const float* x = src + (size_t)row * HID;
    const int t = threadIdx.x;  // 0..511

    // bit-reversed load (imag = 0)
    #pragma unroll
    for (int i = t; i < 1024; i += 512) {
        int r = __brev((unsigned)i) >> 22;
        sh[r] = make_float2(x[i], 0.0f);
    }
    __syncthreads();

    // 10 radix-2 DIT stages, forward (e^{-i...}) convention == jnp.fft.rfft
    #pragma unroll
    for (int s = 0; s < 10; s++) {
        const int len = 1 << s;
        const int j  = t & (len - 1);
        const int i0 = ((t >> s) << (s + 1)) + j;
        const int i1 = i0 + len;
        const float ang = -3.14159265358979323846f * (float)j / (float)len;
        float ws, wc;
        sincosf(ang, &ws, &wc);
        float2 u = sh[i0];
        float2 v = sh[i1];
        float vr = v.x * wc - v.y * ws;
        float vi = v.x * ws + v.y * wc;
        sh[i0] = make_float2(u.x + vr, u.y + vi);
        sh[i1] = make_float2(u.x - vr, u.y - vi);
        __syncthreads();
    }

    // cos(phase) = re/|z|, sin(phase) = im/|z|  (atan2-free)
    float* o = dst + (size_t)row * KP;
    for (int f = t; f < NFREQ; f += 512) {
        float2 z = sh[f];
        float m = sqrtf(z.x * z.x + z.y * z.y);
        float c, sn;
        if (m > 1e-30f) { float inv = 1.0f / m; c = z.x * inv; sn = z.y * inv; }
        else            { c = 1.0f; sn = 0.0f; }   // atan2(0,0)=0 convention
        o[f]         = c;
        o[NFREQ + f] = sn;
    }
    if (t < KP - 2 * NFREQ) o[2 * NFREQ + t] = 0.0f;   // zero K-pad
}

// ---------------------------------------------------------------------------
// 2) scores[b,i,j] = dot(g_qn[b,i,:], g_kn[b,j,:]) / 513 + 1     (C = A*B^T)
//    128x128 tile, BK=8, 8x8 per thread, 256 threads.
// ---------------------------------------------------------------------------
__global__ __launch_bounds__(256) void gemm_nt_scores() {
    __shared__ float As[8][128];
    __shared__ float Bs[8][128];
    const int b = blockIdx.z;
    const float* A = g_qn + (size_t)b * SEQ * KP;
    const float* B = g_kn + (size_t)b * SEQ * KP;
    float* C = g_w + (size_t)b * SEQ * SEQ;

    const int row0 = blockIdx.y * 128;
    const int col0 = blockIdx.x * 128;
    const int tid = threadIdx.x;
    const int lrow = tid >> 1;           // 0..127
    const int lk   = (tid & 1) * 4;      // 0 or 4
    const int ty = tid >> 4, tx = tid & 15;

    float acc[8][8] = {};
    for (int k0 = 0; k0 < KP; k0 += 8) {
        float4 av = *(const float4*)(A + (size_t)(row0 + lrow) * KP + k0 + lk);
        float4 bv = *(const float4*)(B + (size_t)(col0 + lrow) * KP + k0 + lk);
        As[lk + 0][lrow] = av.x; As[lk + 1][lrow] = av.y;
        As[lk + 2][lrow] = av.z; As[lk + 3][lrow] = av.w;
        Bs[lk + 0][lrow] = bv.x; Bs[lk + 1][lrow] = bv.y;
        Bs[lk + 2][lrow] = bv.z; Bs[lk + 3][lrow] = bv.w;
        __syncthreads();
        #pragma unroll
        for (int kk = 0; kk < 8; kk++) {
            float a[8], bb[8];
            #pragma unroll
            for (int i = 0; i < 8; i++) a[i]  = As[kk][ty * 8 + i];
            #pragma unroll
            for (int j = 0; j < 8; j++) bb[j] = Bs[kk][tx * 8 + j];
            #pragma unroll
            for (int i = 0; i < 8; i++)
                #pragma unroll
                for (int j = 0; j < 8; j++)
                    acc[i][j] += a[i] * bb[j];
        }
        __syncthreads();
    }
    const float scale = 1.0f / 513.0f;
    #pragma unroll
    for (int i = 0; i < 8; i++) {
        float* cr = C + (size_t)(row0 + ty * 8 + i) * SEQ + col0 + tx * 8;
        #pragma unroll
        for (int j = 0; j < 8; j += 4) {
            float4 v = make_float4(acc[i][j] * scale + 1.0f, acc[i][j+1] * scale + 1.0f,
                                   acc[i][j+2] * scale + 1.0f, acc[i][j+3] * scale + 1.0f);
            *(float4*)(cr + j) = v;
        }
    }
}

// ---------------------------------------------------------------------------
// 3) row softmax over 2048, in place in g_w, optional copy to weights output
// ---------------------------------------------------------------------------
__global__ __launch_bounds__(256) void softmax_kernel(float* __restrict__ Wout) {
    __shared__ float red[8];
    const int row = blockIdx.x;
    float* p = g_w + (size_t)row * SEQ;
    const int t = threadIdx.x;
    const int warp = t >> 5, lane = t & 31;

    float4 a = *(float4*)(p + 4 * t);
    float4 b = *(float4*)(p + 1024 + 4 * t);
    float m = fmaxf(fmaxf(fmaxf(a.x, a.y), fmaxf(a.z, a.w)),
                    fmaxf(fmaxf(b.x, b.y), fmaxf(b.z, b.w)));
    #pragma unroll
    for (int o = 16; o > 0; o >>= 1) m = fmaxf(m, __shfl_xor_sync(0xffffffffu, m, o));
    if (lane == 0) red[warp] = m;
    __syncthreads();
    if (warp == 0) {
        float v = red[lane & 7];
        #pragma unroll
        for (int o = 4; o > 0; o >>= 1) v = fmaxf(v, __shfl_xor_sync(0xffffffffu, v, o));
        red[lane & 7] = v;
    }
    __syncthreads();
    m = red[0];

    a.x = __expf(a.x - m); a.y = __expf(a.y - m); a.z = __expf(a.z - m); a.w = __expf(a.w - m);
    b.x = __expf(b.x - m); b.y = __expf(b.y - m); b.z = __expf(b.z - m); b.w = __expf(b.w - m);
    float s = a.x + a.y + a.z + a.w + b.x + b.y + b.z + b.w;
    #pragma unroll
    for (int o = 16; o > 0; o >>= 1) s += __shfl_xor_sync(0xffffffffu, s, o);
    __syncthreads();
    if (lane == 0) red[warp] = s;
    __syncthreads();
    if (warp == 0) {
        float v = red[lane & 7];
        #pragma unroll
        for (int o = 4; o > 0; o >>= 1) v += __shfl_xor_sync(0xffffffffu, v, o);
        red[lane & 7] = v;
    }
    __syncthreads();
    const float inv = 1.0f / red[0];

    a.x *= inv; a.y *= inv; a.z *= inv; a.w *= inv;
    b.x *= inv; b.y *= inv; b.z *= inv; b.w *= inv;
    *(float4*)(p + 4 * t) = a;
    *(float4*)(p + 1024 + 4 * t) = b;
    if (Wout) {
        float* q = Wout + (size_t)row * SEQ;
        *(float4*)(q + 4 * t) = a;
        *(float4*)(q + 1024 + 4 * t) = b;
    }
}

// ---------------------------------------------------------------------------
// 4) output[b] = weights[b] @ V[b]   (C = A*B, A:[S,S], B:[S,H])
// ---------------------------------------------------------------------------
__global__ __launch_bounds__(256) void gemm_nn_out(const float* __restrict__ Vin,
                                                   float* __restrict__ Oall) {
    __shared__ float As[8][128];
    __shared__ float Bs[8][128];
    const int b = blockIdx.z;
    const float* A = g_w + (size_t)b * SEQ * SEQ;
    const float* B = Vin + (size_t)b * SEQ * HID;
    float* C = Oall + (size_t)b * SEQ * HID;

    const int row0 = blockIdx.y * 128;
    const int col0 = blockIdx.x * 128;
    const int tid = threadIdx.x;
    const int lrow = tid >> 1, lk = (tid & 1) * 4;    // A load (transpose to smem)
    const int bkr = tid >> 5, bc = (tid & 31) * 4;    // B load (direct)
    const int ty = tid >> 4, tx = tid & 15;

    float acc[8][8] = {};
    for (int k0 = 0; k0 < SEQ; k0 += 8) {
        float4 av = *(const float4*)(A + (size_t)(row0 + lrow) * SEQ + k0 + lk);
        float4 bv = *(const float4*)(B + (size_t)(k0 + bkr) * HID + col0 + bc);
        As[lk + 0][lrow] = av.x; As[lk + 1][lrow] = av.y;
        As[lk + 2][lrow] = av.z; As[lk + 3][lrow] = av.w;
        *(float4*)&Bs[bkr][bc] = bv;
        __syncthreads();
        #pragma unroll
        for (int kk = 0; kk < 8; kk++) {
            float a[8], bb[8];
            #pragma unroll
            for (int i = 0; i < 8; i++) a[i]  = As[kk][ty * 8 + i];
            #pragma unroll
            for (int j = 0; j < 8; j++) bb[j] = Bs[kk][tx * 8 + j];
            #pragma unroll
            for (int i = 0; i < 8; i++)
                #pragma unroll
                for (int j = 0; j < 8; j++)
                    acc[i][j] += a[i] * bb[j];
        }
        __syncthreads();
    }
    #pragma unroll
    for (int i = 0; i < 8; i++) {
        float* cr = C + (size_t)(row0 + ty * 8 + i) * HID + col0 + tx * 8;
        *(float4*)(cr + 0) = make_float4(acc[i][0], acc[i][1], acc[i][2], acc[i][3]);
        *(float4*)(cr + 4) = make_float4(acc[i][4], acc[i][5], acc[i][6], acc[i][7]);
    }
}

// ---------------------------------------------------------------------------
extern "C" void kernel_launch(void* const* d_in, const int* in_sizes, int n_in,
                              void* d_out, int out_size) {
    const float* Q = (const float*)d_in[0];
    const float* K = (const float*)d_in[1];
    const float* V = (const float*)d_in[2];

    const long BSH = (long)BATCH * SEQ * HID;   //  8388608
    const long BSS = (long)BATCH * SEQ * SEQ;   // 16777216
    float* out = (float*)d_out;
    float* out_attn = nullptr;
    float* out_w = nullptr;
    if ((long)out_size >= BSH + BSS)      { out_attn = out; out_w = out + BSH; }
    else if ((long)out_size == BSS)       { out_w = out; }
    else                                  { out_attn = out; }

    fft_phase_kernel<<<dim3(ROWS, 2), 512>>>(Q, K);
    gemm_nt_scores<<<dim3(SEQ / 128, SEQ / 128, BATCH), 256>>>();
    softmax_kernel<<<dim3(ROWS), 256>>>(out_w);
    if (out_attn)
        gemm_nn_out<<<dim3(HID / 128, SEQ / 128, BATCH), 256>>>(V, out_attn);
}

// round 17
// speedup vs baseline: 2.7034x; 2.7034x over previous
#include <cuda_runtime.h>
#include <cuda_bf16.h>
#include <cstdint>

#define BATCH 4
#define SEQ   2048
#define HID   1024
#define NFREQ 513
#define KP    1056              // 2*513=1026 padded to multiple of 32
#define ROWS  (BATCH * SEQ)

// ---------------- scratch (static device globals; allocation-free) ----------
__device__ float g_qn[(size_t)ROWS * KP];            // tf32-rounded [cos|sin|0]
__device__ float g_kn[(size_t)ROWS * KP];
__device__ float g_w [(size_t)BATCH * SEQ * SEQ];    // scores -> weights (in place)

__device__ __forceinline__ float tf32r(float x) {
    uint32_t u;
    asm("cvt.rna.tf32.f32 %0, %1;" : "=r"(u) : "f"(x));
    return __uint_as_float(u);
}
__device__ __forceinline__ float4 tf32r4(float4 v) {
    return make_float4(tf32r(v.x), tf32r(v.y), tf32r(v.z), tf32r(v.w));
}

// mma.sync m16n8k8 tf32: D = A*B + D (fp32 accum)
__device__ __forceinline__ void mma_tf32(float* c, const uint32_t* a, const uint32_t* b) {
    asm volatile(
        "mma.sync.aligned.m16n8k8.row.col.f32.tf32.tf32.f32 "
        "{%0,%1,%2,%3}, {%4,%5,%6,%7}, {%8,%9}, {%0,%1,%2,%3};"
        : "+f"(c[0]), "+f"(c[1]), "+f"(c[2]), "+f"(c[3])
        : "r"(a[0]), "r"(a[1]), "r"(a[2]), "r"(a[3]), "r"(b[0]), "r"(b[1]));
}

// ---------------------------------------------------------------------------
// 1) FFT-1024 per row -> unit cos/sin rows (tf32-rounded fp32), padded to KP
// ---------------------------------------------------------------------------
__global__ void fft_phase_kernel(const float* __restrict__ Q,
                                 const float* __restrict__ Kin) {
    __shared__ float2 sh[1024];
    const int row = blockIdx.x;
    const float* src = (blockIdx.y == 0) ? Q : Kin;
    float* dst = (blockIdx.y == 0) ? g_qn : g_kn;
    const float* x = src + (size_t)row * HID;
    const int t = threadIdx.x;

    #pragma unroll
    for (int i = t; i < 1024; i += 512) {
        int r = __brev((unsigned)i) >> 22;
        sh[r] = make_float2(x[i], 0.0f);
    }
    __syncthreads();
    #pragma unroll
    for (int s = 0; s < 10; s++) {
        const int len = 1 << s;
        const int j = t & (len - 1);
        const int i0 = ((t >> s) << (s + 1)) + j;
        const int i1 = i0 + len;
        float ws, wc;
        sincosf(-3.14159265358979323846f * (float)j / (float)len, &ws, &wc);
        float2 u = sh[i0], v = sh[i1];
        float vr = v.x * wc - v.y * ws;
        float vi = v.x * ws + v.y * wc;
        sh[i0] = make_float2(u.x + vr, u.y + vi);
        sh[i1] = make_float2(u.x - vr, u.y - vi);
        __syncthreads();
    }
    float* o = dst + (size_t)row * KP;
    for (int f = t; f < NFREQ; f += 512) {
        float2 z = sh[f];
        float m = sqrtf(z.x * z.x + z.y * z.y);
        float c, sn;
        if (m > 1e-30f) { float inv = 1.0f / m; c = z.x * inv; sn = z.y * inv; }
        else            { c = 1.0f; sn = 0.0f; }
        o[f]         = tf32r(c);
        o[NFREQ + f] = tf32r(sn);
    }
    for (int f = 2 * NFREQ + t; f < KP; f += 512) o[f] = 0.0f;
}

// ---------------------------------------------------------------------------
// 2) scores = (Qn @ Kn^T)/513 + 1   — tf32 mma.sync, 128x128 tile, BK=32
//    smem: As[2][128][36], Bs[2][128][36]  (both operands row-major, k inner)
// ---------------------------------------------------------------------------
__global__ __launch_bounds__(256) void gemm_scores_tf32() {
    extern __shared__ float sm[];
    float* As = sm;                       // [2][128][36]
    float* Bs = sm + 2 * 128 * 36;        // [2][128][36]
    const int tid = threadIdx.x, wid = tid >> 5, lane = tid & 31;
    const int b = blockIdx.z, row0 = blockIdx.y * 128, col0 = blockIdx.x * 128;
    const int warp_m = wid & 1, warp_n = wid >> 1;

    const float* A = g_qn + (size_t)(b * SEQ + row0) * KP;
    const float* B = g_kn + (size_t)(b * SEQ + col0) * KP;

    float acc[4][4][4] = {};
    float4 pa[4], pb[4];

    // chunk 0 -> buffer 0
    #pragma unroll
    for (int i = 0; i < 4; i++) {
        int j = tid + i * 256, r = j >> 3, s = j & 7;
        pa[i] = *(const float4*)(A + (size_t)r * KP + s * 4);
        pb[i] = *(const float4*)(B + (size_t)r * KP + s * 4);
    }
    #pragma unroll
    for (int i = 0; i < 4; i++) {
        int j = tid + i * 256, r = j >> 3, s = j & 7;
        *(float4*)(As + r * 36 + s * 4) = pa[i];
        *(float4*)(Bs + r * 36 + s * 4) = pb[i];
    }
    __syncthreads();

    const int NC = KP / 32;   // 33
    for (int c = 0; c < NC; c++) {
        const int buf = c & 1;
        if (c + 1 < NC) {
            const int k0 = (c + 1) * 32;
            #pragma unroll
            for (int i = 0; i < 4; i++) {
                int j = tid + i * 256, r = j >> 3, s = j & 7;
                pa[i] = *(const float4*)(A + (size_t)r * KP + k0 + s * 4);
                pb[i] = *(const float4*)(B + (size_t)r * KP + k0 + s * 4);
            }
        }
        const float* Ab = As + buf * 128 * 36;
        const float* Bb = Bs + buf * 128 * 36;
        #pragma unroll
        for (int kk = 0; kk < 32; kk += 8) {
            uint32_t af[4][4], bf[4][2];
            #pragma unroll
            for (int mt = 0; mt < 4; mt++) {
                int r = warp_m * 64 + mt * 16 + (lane >> 2);
                int cc = kk + (lane & 3);
                af[mt][0] = __float_as_uint(Ab[r * 36 + cc]);
                af[mt][1] = __float_as_uint(Ab[(r + 8) * 36 + cc]);
                af[mt][2] = __float_as_uint(Ab[r * 36 + cc + 4]);
                af[mt][3] = __float_as_uint(Ab[(r + 8) * 36 + cc + 4]);
            }
            #pragma unroll
            for (int nt = 0; nt < 4; nt++) {
                int n = warp_n * 32 + nt * 8 + (lane >> 2);
                int cc = kk + (lane & 3);
                bf[nt][0] = __float_as_uint(Bb[n * 36 + cc]);
                bf[nt][1] = __float_as_uint(Bb[n * 36 + cc + 4]);
            }
            #pragma unroll
            for (int mt = 0; mt < 4; mt++)
                #pragma unroll
                for (int nt = 0; nt < 4; nt++)
                    mma_tf32(acc[mt][nt], af[mt], bf[nt]);
        }
        if (c + 1 < NC) {
            __syncthreads();
            float* An = As + (buf ^ 1) * 128 * 36;
            float* Bn = Bs + (buf ^ 1) * 128 * 36;
            #pragma unroll
            for (int i = 0; i < 4; i++) {
                int j = tid + i * 256, r = j >> 3, s = j & 7;
                *(float4*)(An + r * 36 + s * 4) = pa[i];
                *(float4*)(Bn + r * 36 + s * 4) = pb[i];
            }
            __syncthreads();
        }
    }

    const float scale = 1.0f / 513.0f;
    float* C = g_w + ((size_t)b * SEQ + row0) * SEQ + col0;
    #pragma unroll
    for (int mt = 0; mt < 4; mt++) {
        int r = warp_m * 64 + mt * 16 + (lane >> 2);
        #pragma unroll
        for (int nt = 0; nt < 4; nt++) {
            int cc = warp_n * 32 + nt * 8 + 2 * (lane & 3);
            float* p = acc[mt][nt];
            *(float2*)(C + (size_t)r * SEQ + cc) =
                make_float2(p[0] * scale + 1.0f, p[1] * scale + 1.0f);
            *(float2*)(C + (size_t)(r + 8) * SEQ + cc) =
                make_float2(p[2] * scale + 1.0f, p[3] * scale + 1.0f);
        }
    }
}

// ---------------------------------------------------------------------------
// 3) row softmax, normalized fp32 in place in g_w (+ optional Wout copy)
// ---------------------------------------------------------------------------
__global__ __launch_bounds__(256) void softmax_kernel(float* __restrict__ Wout) {
    __shared__ float red[8];
    const int row = blockIdx.x;
    float* p = g_w + (size_t)row * SEQ;
    const int t = threadIdx.x, warp = t >> 5, lane = t & 31;

    float4 a = *(float4*)(p + 4 * t);
    float4 bq = *(float4*)(p + 1024 + 4 * t);
    float m = fmaxf(fmaxf(fmaxf(a.x, a.y), fmaxf(a.z, a.w)),
                    fmaxf(fmaxf(bq.x, bq.y), fmaxf(bq.z, bq.w)));
    #pragma unroll
    for (int o = 16; o > 0; o >>= 1) m = fmaxf(m, __shfl_xor_sync(~0u, m, o));
    if (lane == 0) red[warp] = m;
    __syncthreads();
    if (warp == 0) {
        float v = red[lane & 7];
        #pragma unroll
        for (int o = 4; o > 0; o >>= 1) v = fmaxf(v, __shfl_xor_sync(~0u, v, o));
        red[lane & 7] = v;
    }
    __syncthreads();
    m = red[0];

    a.x = __expf(a.x - m); a.y = __expf(a.y - m); a.z = __expf(a.z - m); a.w = __expf(a.w - m);
    bq.x = __expf(bq.x - m); bq.y = __expf(bq.y - m); bq.z = __expf(bq.z - m); bq.w = __expf(bq.w - m);
    float s = a.x + a.y + a.z + a.w + bq.x + bq.y + bq.z + bq.w;
    #pragma unroll
    for (int o = 16; o > 0; o >>= 1) s += __shfl_xor_sync(~0u, s, o);
    __syncthreads();
    if (lane == 0) red[warp] = s;
    __syncthreads();
    if (warp == 0) {
        float v = red[lane & 7];
        #pragma unroll
        for (int o = 4; o > 0; o >>= 1) v += __shfl_xor_sync(~0u, v, o);
        red[lane & 7] = v;
    }
    __syncthreads();
    const float inv = 1.0f / red[0];

    a.x *= inv; a.y *= inv; a.z *= inv; a.w *= inv;
    bq.x *= inv; bq.y *= inv; bq.z *= inv; bq.w *= inv;
    *(float4*)(p + 4 * t) = a;
    *(float4*)(p + 1024 + 4 * t) = bq;
    if (Wout) {
        float* q = Wout + (size_t)row * SEQ;
        *(float4*)(q + 4 * t) = a;
        *(float4*)(q + 1024 + 4 * t) = bq;
    }
}

// ---------------------------------------------------------------------------
// 4) output = W @ V — tf32 mma.sync, 128x128 tile, BK=32
//    tf32 rounding fused into the operand loaders (registers, pre-STS).
//    smem: As[2][128][36] (W, m-major), Bs[2][32][136] (V, k-major)
// ---------------------------------------------------------------------------
__global__ __launch_bounds__(256) void gemm_out_tf32(const float* __restrict__ Vin,
                                                     float* __restrict__ Oall) {
    extern __shared__ float sm[];
    float* As = sm;                        // [2][128][36]
    float* Bs = sm + 2 * 128 * 36;         // [2][32][136]
    const int tid = threadIdx.x, wid = tid >> 5, lane = tid & 31;
    const int b = blockIdx.z, row0 = blockIdx.y * 128, col0 = blockIdx.x * 128;
    const int warp_m = wid & 1, warp_n = wid >> 1;

    const float* A = g_w + ((size_t)b * SEQ + row0) * SEQ;
    const float* B = Vin + (size_t)b * SEQ * HID + col0;

    float acc[4][4][4] = {};
    float4 pa[4], pb[4];

    #pragma unroll
    for (int i = 0; i < 4; i++) {
        int j = tid + i * 256;
        int ra = j >> 3, sa = j & 7;
        pa[i] = tf32r4(*(const float4*)(A + (size_t)ra * SEQ + sa * 4));
        int rb = j >> 5, sb = j & 31;
        pb[i] = tf32r4(*(const float4*)(B + (size_t)rb * HID + sb * 4));
    }
    #pragma unroll
    for (int i = 0; i < 4; i++) {
        int j = tid + i * 256;
        int ra = j >> 3, sa = j & 7;
        *(float4*)(As + ra * 36 + sa * 4) = pa[i];
        int rb = j >> 5, sb = j & 31;
        *(float4*)(Bs + rb * 136 + sb * 4) = pb[i];
    }
    __syncthreads();

    const int NC = SEQ / 32;   // 64
    for (int c = 0; c < NC; c++) {
        const int buf = c & 1;
        if (c + 1 < NC) {
            const int k0 = (c + 1) * 32;
            #pragma unroll
            for (int i = 0; i < 4; i++) {
                int j = tid + i * 256;
                int ra = j >> 3, sa = j & 7;
                pa[i] = tf32r4(*(const float4*)(A + (size_t)ra * SEQ + k0 + sa * 4));
                int rb = j >> 5, sb = j & 31;
                pb[i] = tf32r4(*(const float4*)(B + (size_t)(k0 + rb) * HID + sb * 4));
            }
        }
        const float* Ab = As + buf * 128 * 36;
        const float* Bb = Bs + buf * 32 * 136;
        #pragma unroll
        for (int kk = 0; kk < 32; kk += 8) {
            uint32_t af[4][4], bf[4][2];
            #pragma unroll
            for (int mt = 0; mt < 4; mt++) {
                int r = warp_m * 64 + mt * 16 + (lane >> 2);
                int cc = kk + (lane & 3);
                af[mt][0] = __float_as_uint(Ab[r * 36 + cc]);
                af[mt][1] = __float_as_uint(Ab[(r + 8) * 36 + cc]);
                af[mt][2] = __float_as_uint(Ab[r * 36 + cc + 4]);
                af[mt][3] = __float_as_uint(Ab[(r + 8) * 36 + cc + 4]);
            }
            #pragma unroll
            for (int nt = 0; nt < 4; nt++) {
                int n = warp_n * 32 + nt * 8 + (lane >> 2);
                int kr = kk + (lane & 3);
                bf[nt][0] = __float_as_uint(Bb[kr * 136 + n]);
                bf[nt][1] = __float_as_uint(Bb[(kr + 4) * 136 + n]);
            }
            #pragma unroll
            for (int mt = 0; mt < 4; mt++)
                #pragma unroll
                for (int nt = 0; nt < 4; nt++)
                    mma_tf32(acc[mt][nt], af[mt], bf[nt]);
        }
        if (c + 1 < NC) {
            __syncthreads();
            float* An = As + (buf ^ 1) * 128 * 36;
            float* Bn = Bs + (buf ^ 1) * 32 * 136;
            #pragma unroll
            for (int i = 0; i < 4; i++) {
                int j = tid + i * 256;
                int ra = j >> 3, sa = j & 7;
                *(float4*)(An + ra * 36 + sa * 4) = pa[i];
                int rb = j >> 5, sb = j & 31;
                *(float4*)(Bn + rb * 136 + sb * 4) = pb[i];
            }
            __syncthreads();
        }
    }

    float* C = Oall + ((size_t)b * SEQ + row0) * HID + col0;
    #pragma unroll
    for (int mt = 0; mt < 4; mt++) {
        int r = warp_m * 64 + mt * 16 + (lane >> 2);
        #pragma unroll
        for (int nt = 0; nt < 4; nt++) {
            int cc = warp_n * 32 + nt * 8 + 2 * (lane & 3);
            float* p = acc[mt][nt];
            *(float2*)(C + (size_t)r * HID + cc) = make_float2(p[0], p[1]);
            *(float2*)(C + (size_t)(r + 8) * HID + cc) = make_float2(p[2], p[3]);
        }
    }
}

// ---------------------------------------------------------------------------
extern "C" void kernel_launch(void* const* d_in, const int* in_sizes, int n_in,
                              void* d_out, int out_size) {
    const float* Q = (const float*)d_in[0];
    const float* K = (const float*)d_in[1];
    const float* V = (const float*)d_in[2];

    const long BSH = (long)BATCH * SEQ * HID;   //  8388608
    const long BSS = (long)BATCH * SEQ * SEQ;   // 16777216
    float* out = (float*)d_out;
    float* out_attn = nullptr;
    float* out_w = nullptr;
    if ((long)out_size >= BSH + BSS)      { out_attn = out; out_w = out + BSH; }
    else if ((long)out_size == BSS)       { out_w = out; }
    else                                  { out_attn = out; }

    const int SMEM_SC = 2 * 128 * 36 * 4 * 2;               // 73728
    const int SMEM_OUT = (2 * 128 * 36 + 2 * 32 * 136) * 4; // 71680
    cudaFuncSetAttribute(gemm_scores_tf32, cudaFuncAttributeMaxDynamicSharedMemorySize, SMEM_SC);
    cudaFuncSetAttribute(gemm_out_tf32,    cudaFuncAttributeMaxDynamicSharedMemorySize, SMEM_OUT);

    fft_phase_kernel<<<dim3(ROWS, 2), 512>>>(Q, K);
    gemm_scores_tf32<<<dim3(SEQ / 128, SEQ / 128, BATCH), 256, SMEM_SC>>>();
    softmax_kernel<<<dim3(BATCH * SEQ), 256>>>(out_w);
    if (out_attn)
        gemm_out_tf32<<<dim3(HID / 128, SEQ / 128, BATCH), 256, SMEM_OUT>>>(V, out_attn);
}